// round 1
// baseline (speedup 1.0000x reference)
#include <cuda_runtime.h>
#include <cstdint>

#define T_STEPS 128
#define BATCH   512
#define NLAB    512
#define HID     1024
#define SEM     1024

// Scratch: I1 (then overwritten in-place by spk1), and I2.
__device__ float g_buf1[(size_t)T_STEPS * BATCH * HID];
__device__ float g_buf2[(size_t)T_STEPS * BATCH * SEM];

// ---------------------------------------------------------------------------
// C[M,N] = A[M,K] @ B[N,K]^T  (all fp32, row-major). BM=BN=128, BK=8,
// 256 threads, 8x8 micro-tile per thread.
// ---------------------------------------------------------------------------
__global__ __launch_bounds__(256, 2)
void gemm_tn(const float* __restrict__ A, const float* __restrict__ B,
             float* __restrict__ C, int M, int N, int K)
{
    constexpr int BM = 128, BN = 128, BK = 8;
    __shared__ float As[BK][BM];
    __shared__ float Bs[BK][BN];

    const int tid  = threadIdx.x;
    const size_t mBase = (size_t)blockIdx.y * BM;
    const size_t nBase = (size_t)blockIdx.x * BN;

    // loader mapping: 128 rows x 8 cols per tile, one float4 per thread
    const int lrow = tid >> 1;           // 0..127
    const int lcol = (tid & 1) * 4;      // 0 or 4
    const float* Ag = A + (mBase + (size_t)lrow) * K + lcol;
    const float* Bg = B + (nBase + (size_t)lrow) * K + lcol;

    // compute mapping: 16x16 thread grid of 8x8 tiles
    const int tr = (tid >> 4) * 8;       // 0..120
    const int tc = (tid & 15) * 8;       // 0..120

    float acc[8][8];
#pragma unroll
    for (int i = 0; i < 8; i++)
#pragma unroll
        for (int j = 0; j < 8; j++) acc[i][j] = 0.f;

    for (int k0 = 0; k0 < K; k0 += BK) {
        float4 av = *(const float4*)(Ag + k0);
        float4 bv = *(const float4*)(Bg + k0);
        As[lcol + 0][lrow] = av.x; As[lcol + 1][lrow] = av.y;
        As[lcol + 2][lrow] = av.z; As[lcol + 3][lrow] = av.w;
        Bs[lcol + 0][lrow] = bv.x; Bs[lcol + 1][lrow] = bv.y;
        Bs[lcol + 2][lrow] = bv.z; Bs[lcol + 3][lrow] = bv.w;
        __syncthreads();

#pragma unroll
        for (int kk = 0; kk < BK; kk++) {
            float ar[8], br[8];
            *(float4*)(ar)     = *(const float4*)&As[kk][tr];
            *(float4*)(ar + 4) = *(const float4*)&As[kk][tr + 4];
            *(float4*)(br)     = *(const float4*)&Bs[kk][tc];
            *(float4*)(br + 4) = *(const float4*)&Bs[kk][tc + 4];
#pragma unroll
            for (int i = 0; i < 8; i++)
#pragma unroll
                for (int j = 0; j < 8; j++)
                    acc[i][j] = fmaf(ar[i], br[j], acc[i][j]);
        }
        __syncthreads();
    }

    float* Cp = C + (mBase + tr) * N + nBase + tc;
#pragma unroll
    for (int i = 0; i < 8; i++) {
        *(float4*)(Cp + (size_t)i * N)     = make_float4(acc[i][0], acc[i][1], acc[i][2], acc[i][3]);
        *(float4*)(Cp + (size_t)i * N + 4) = make_float4(acc[i][4], acc[i][5], acc[i][6], acc[i][7]);
    }
}

// ---------------------------------------------------------------------------
// LIF over time: each thread owns one (b, unit) element, walks t = 0..T-1.
// io layout: [(t*BATCH + b) * NUNITS + u]; thread idx = b*NUNITS + u, so the
// per-t address is io[idx + t * BATCH*NUNITS] (NUNITS = 1024 for both layers).
// If WRITE_SPK, overwrite the input current with the binary spike (for GEMM2).
// ---------------------------------------------------------------------------
template <bool WRITE_SPK>
__global__ __launch_bounds__(256)
void lif_kernel(float* __restrict__ io, float* __restrict__ mean_out)
{
    const size_t idx    = (size_t)blockIdx.x * blockDim.x + threadIdx.x;
    const size_t stride = (size_t)BATCH * 1024;

    float v = 0.f;
    float cnt = 0.f;
    float* p = io + idx;
#pragma unroll 8
    for (int t = 0; t < T_STEPS; t++) {
        float x = p[(size_t)t * stride];
        v = fmaf(0.95f, v, x);
        float s = (v > 1.0f) ? 1.0f : 0.0f;
        v *= (1.0f - s);
        if (WRITE_SPK) p[(size_t)t * stride] = s;
        cnt += s;
    }
    mean_out[idx] = cnt * (1.0f / 128.0f);
}

extern "C" void kernel_launch(void* const* d_in, const int* in_sizes, int n_in,
                              void* d_out, int out_size)
{
    const float* spikes = (const float*)d_in[0];   // (T, B, NLAB)
    const float* W1     = (const float*)d_in[1];   // (HID, NLAB)
    const float* W2     = (const float*)d_in[2];   // (SEM, HID)
    float* out = (float*)d_out;                    // [mean1 (B,HID) | mean2 (B,SEM)]

    float *buf1, *buf2;
    cudaGetSymbolAddress((void**)&buf1, g_buf1);
    cudaGetSymbolAddress((void**)&buf2, g_buf2);

    const int M = T_STEPS * BATCH;     // 65536

    // 1) I1 = spikes @ W1^T   (65536 x 1024, K=512)
    {
        dim3 grid(HID / 128, M / 128);
        gemm_tn<<<grid, 256>>>(spikes, W1, buf1, M, HID, NLAB);
    }
    // 2) LIF layer 1 -> spk1 in-place, mean1 -> out[0 : B*HID)
    {
        int n = BATCH * HID;
        lif_kernel<true><<<n / 256, 256>>>(buf1, out);
    }
    // 3) I2 = spk1 @ W2^T   (65536 x 1024, K=1024)
    {
        dim3 grid(SEM / 128, M / 128);
        gemm_tn<<<grid, 256>>>(buf1, W2, buf2, M, SEM, HID);
    }
    // 4) LIF layer 2 -> mean2 -> out[B*HID : )
    {
        int n = BATCH * SEM;
        lif_kernel<false><<<n / 256, 256>>>(buf2, out + (size_t)BATCH * HID);
    }
}

// round 4
// speedup vs baseline: 1.6050x; 1.6050x over previous
#include <cuda_runtime.h>
#include <cuda_bf16.h>
#include <cstdint>

#define T_STEPS 128
#define BATCH   512
#define NLAB    512
#define HID     1024
#define SEM     1024
#define MROWS   (T_STEPS*BATCH)    // 65536

typedef unsigned long long ull;

// ---------------- scratch (device globals; no allocs allowed) ----------------
__device__ __nv_bfloat16 g_spk1[(size_t)MROWS * HID];    // 128 MB layer-1 spikes bf16
__device__ float         g_I   [(size_t)MROWS * HID];    // 256 MB currents (reused L1/L2)
__device__ __nv_bfloat16 g_ws2 [3ull * SEM * HID];       //   6 MB W2 splits

// ============================================================================
// Layer-1 GEMM: bit-exact fp32, sequential ascending-k per output, packed
// fma.rn.f32x2 (each lane an independent IEEE fp32 fma chain).
// C[M,N] = A[M,K] @ B[N,K]^T. BM=BN=128, BK=8, 256 thr, 8x8 tile/thread
// (paired along m: 4x8 ull accumulators).
// ============================================================================
__device__ __forceinline__ ull fma2(ull a, ull b, ull c) {
    ull d;
    asm("fma.rn.f32x2 %0, %1, %2, %3;" : "=l"(d) : "l"(a), "l"(b), "l"(c));
    return d;
}
__device__ __forceinline__ ull pack2(float x) {
    ull d;
    asm("mov.b64 %0, {%1, %2};" : "=l"(d) : "f"(x), "f"(x));
    return d;
}
__device__ __forceinline__ void unpack2(ull v, float& lo, float& hi) {
    asm("mov.b64 {%0, %1}, %2;" : "=f"(lo), "=f"(hi) : "l"(v));
}

__global__ __launch_bounds__(256, 2)
void gemm_f32x2(const float* __restrict__ A, const float* __restrict__ B,
                float* __restrict__ C, int M, int N, int K)
{
    constexpr int BM = 128, BN = 128, BK = 8;
    __shared__ float As[BK][BM];
    __shared__ float Bs[BK][BN];

    const int tid = threadIdx.x;
    const size_t mBase = (size_t)blockIdx.y * BM;
    const size_t nBase = (size_t)blockIdx.x * BN;

    const int lrow = tid >> 1;
    const int lcol = (tid & 1) * 4;
    const float* Ag = A + (mBase + (size_t)lrow) * K + lcol;
    const float* Bg = B + (nBase + (size_t)lrow) * K + lcol;

    const int tr = (tid >> 4) * 8;   // m offset of 8-row block
    const int tc = (tid & 15) * 8;   // n offset of 8-col block

    ull acc2[4][8];
#pragma unroll
    for (int i = 0; i < 4; i++)
#pragma unroll
        for (int j = 0; j < 8; j++) acc2[i][j] = 0ull;

    for (int k0 = 0; k0 < K; k0 += BK) {
        float4 av = *(const float4*)(Ag + k0);
        float4 bv = *(const float4*)(Bg + k0);
        As[lcol + 0][lrow] = av.x; As[lcol + 1][lrow] = av.y;
        As[lcol + 2][lrow] = av.z; As[lcol + 3][lrow] = av.w;
        Bs[lcol + 0][lrow] = bv.x; Bs[lcol + 1][lrow] = bv.y;
        Bs[lcol + 2][lrow] = bv.z; Bs[lcol + 3][lrow] = bv.w;
        __syncthreads();

#pragma unroll
        for (int kk = 0; kk < BK; kk++) {
            // a pairs: rows (tr+2i, tr+2i+1) -> 32B contiguous in As
            ull a2[4];
            *(uint4*)(a2)     = *(const uint4*)&As[kk][tr];
            *(uint4*)(a2 + 2) = *(const uint4*)&As[kk][tr + 4];
            float br[8];
            *(float4*)(br)     = *(const float4*)&Bs[kk][tc];
            *(float4*)(br + 4) = *(const float4*)&Bs[kk][tc + 4];
            ull b2[8];
#pragma unroll
            for (int j = 0; j < 8; j++) b2[j] = pack2(br[j]);
#pragma unroll
            for (int i = 0; i < 4; i++)
#pragma unroll
                for (int j = 0; j < 8; j++)
                    acc2[i][j] = fma2(a2[i], b2[j], acc2[i][j]);
        }
        __syncthreads();
    }

#pragma unroll
    for (int i = 0; i < 4; i++) {
        float lo[8], hi[8];
#pragma unroll
        for (int j = 0; j < 8; j++) unpack2(acc2[i][j], lo[j], hi[j]);
        float* p0 = C + (mBase + tr + 2 * i)     * N + nBase + tc;
        float* p1 = C + (mBase + tr + 2 * i + 1) * N + nBase + tc;
        *(float4*)(p0)     = make_float4(lo[0], lo[1], lo[2], lo[3]);
        *(float4*)(p0 + 4) = make_float4(lo[4], lo[5], lo[6], lo[7]);
        *(float4*)(p1)     = make_float4(hi[0], hi[1], hi[2], hi[3]);
        *(float4*)(p1 + 4) = make_float4(hi[4], hi[5], hi[6], hi[7]);
    }
}

// ============================================================================
// Layer-2 GEMM: HMMA bf16 3-split (exact products; tree-order fp32 accum).
// ============================================================================
#define BM2 128
#define BN2 128
#define BK2 32
#define STAGES 4
#define PADK  (BK2 + 8)
#define ROWB  (PADK * 2)               // 80 B/row
#define A_BYTES  (BM2 * ROWB)
#define B_SPLIT  (BN2 * ROWB)
#define STAGE_BYTES (A_BYTES + 3 * B_SPLIT)
#define SMEM_BYTES  (STAGES * STAGE_BYTES)   // 163840

__device__ __forceinline__ uint32_t s2u(const void* p) {
    uint32_t a;
    asm("{ .reg .u64 t; cvta.to.shared.u64 t, %1; cvt.u32.u64 %0, t; }" : "=r"(a) : "l"(p));
    return a;
}
__device__ __forceinline__ void cpa16(uint32_t dst, const void* src) {
    asm volatile("cp.async.cg.shared.global [%0], [%1], 16;" :: "r"(dst), "l"(src) : "memory");
}
__device__ __forceinline__ void ldsm_x4(uint32_t* r, uint32_t addr) {
    asm volatile("ldmatrix.sync.aligned.m8n8.x4.shared.b16 {%0,%1,%2,%3}, [%4];"
                 : "=r"(r[0]), "=r"(r[1]), "=r"(r[2]), "=r"(r[3]) : "r"(addr));
}
__device__ __forceinline__ void ldsm_x2(uint32_t* r, uint32_t addr) {
    asm volatile("ldmatrix.sync.aligned.m8n8.x2.shared.b16 {%0,%1}, [%2];"
                 : "=r"(r[0]), "=r"(r[1]) : "r"(addr));
}
__device__ __forceinline__ void mma16816(float* c, const uint32_t* a, const uint32_t* b) {
    asm volatile("mma.sync.aligned.m16n8k16.row.col.f32.bf16.bf16.f32 "
                 "{%0,%1,%2,%3}, {%4,%5,%6,%7}, {%8,%9}, {%0,%1,%2,%3};"
                 : "+f"(c[0]), "+f"(c[1]), "+f"(c[2]), "+f"(c[3])
                 : "r"(a[0]), "r"(a[1]), "r"(a[2]), "r"(a[3]), "r"(b[0]), "r"(b[1]));
}

template <int K>
__global__ void __launch_bounds__(256, 1)
gemm3s(const __nv_bfloat16* __restrict__ A,
       const __nv_bfloat16* __restrict__ W,    // [3][1024][K]
       float* __restrict__ C)
{
    extern __shared__ char smem[];
    const uint32_t sb = s2u(smem);
    const int tid = threadIdx.x;
    const size_t mBase = (size_t)blockIdx.y * BM2;
    const size_t nBase = (size_t)blockIdx.x * BN2;
    constexpr int NC = K / BK2;

    auto load_stage = [&](int chunk, int stage) {
        const uint32_t s0 = sb + stage * STAGE_BYTES;
        const int k0 = chunk * BK2;
#pragma unroll
        for (int j = 0; j < 2; ++j) {
            int c = tid * 2 + j;
            int row = c >> 2, kc = c & 3;
            cpa16(s0 + row * ROWB + kc * 16,
                  (const char*)(A + (mBase + row) * (size_t)K + k0) + kc * 16);
        }
#pragma unroll
        for (int j = 0; j < 6; ++j) {
            int c = tid + j * 256;
            int sp = c >> 9, rem = c & 511;
            int row = rem >> 2, kc = rem & 3;
            cpa16(s0 + A_BYTES + sp * B_SPLIT + row * ROWB + kc * 16,
                  (const char*)(W + sp * (size_t)1024 * K + (nBase + row) * (size_t)K + k0) + kc * 16);
        }
        asm volatile("cp.async.commit_group;" ::: "memory");
    };

    const int wid  = tid >> 5, lane = tid & 31;
    const int wm = (wid >> 1) * 32;
    const int wn = (wid & 1) * 64;

    float acc[2][8][4];
#pragma unroll
    for (int mi = 0; mi < 2; ++mi)
#pragma unroll
        for (int ni = 0; ni < 8; ++ni)
#pragma unroll
            for (int q = 0; q < 4; ++q) acc[mi][ni][q] = 0.f;

    for (int s = 0; s < STAGES - 1; ++s) load_stage(s, s);

    for (int i = 0; i < NC; ++i) {
        const int nxt = i + STAGES - 1;
        if (nxt < NC) load_stage(nxt, nxt & (STAGES - 1));
        else asm volatile("cp.async.commit_group;" ::: "memory");
        asm volatile("cp.async.wait_group %0;" :: "n"(STAGES - 2) : "memory");
        __syncthreads();

        const uint32_t s0 = sb + (i & (STAGES - 1)) * STAGE_BYTES;
#pragma unroll
        for (int ks = 0; ks < 2; ++ks) {
            const int k = ks * 16;
            uint32_t af[2][4];
#pragma unroll
            for (int mi = 0; mi < 2; ++mi) {
                uint32_t addr = s0 + (uint32_t)(wm + mi * 16 + (lane & 15)) * ROWB
                              + (uint32_t)(k + 8 * (lane >> 4)) * 2;
                ldsm_x4(af[mi], addr);
            }
#pragma unroll
            for (int sp = 0; sp < 3; ++sp) {
                const uint32_t bbase = s0 + A_BYTES + sp * B_SPLIT;
#pragma unroll
                for (int ni = 0; ni < 8; ++ni) {
                    uint32_t bf[2];
                    uint32_t addr = bbase + (uint32_t)(wn + ni * 8 + (lane & 7)) * ROWB
                                  + (uint32_t)(k + 8 * ((lane >> 3) & 1)) * 2;
                    ldsm_x2(bf, addr);
                    mma16816(acc[0][ni], af[0], bf);
                    mma16816(acc[1][ni], af[1], bf);
                }
            }
        }
        __syncthreads();
    }

    const int r0 = lane >> 2, c0 = (lane & 3) * 2;
#pragma unroll
    for (int mi = 0; mi < 2; ++mi)
#pragma unroll
        for (int ni = 0; ni < 8; ++ni) {
            float* p = C + (mBase + wm + mi * 16 + r0) * 1024 + nBase + wn + ni * 8 + c0;
            *(float2*)p              = make_float2(acc[mi][ni][0], acc[mi][ni][1]);
            *(float2*)(p + 8 * 1024) = make_float2(acc[mi][ni][2], acc[mi][ni][3]);
        }
}

// ---------------------------------------------------------------------------
template <bool WRITE_SPK>
__global__ void __launch_bounds__(256)
lif_kernel(const float* __restrict__ I, __nv_bfloat16* __restrict__ spk,
           float* __restrict__ mean_out)
{
    const size_t idx    = (size_t)blockIdx.x * blockDim.x + threadIdx.x;
    const size_t stride = (size_t)BATCH * 1024;
    float v = 0.f, cnt = 0.f;
#pragma unroll 8
    for (int t = 0; t < T_STEPS; t++) {
        float x = I[idx + (size_t)t * stride];
        v = fmaf(0.95f, v, x);
        float s = (v > 1.0f) ? 1.0f : 0.0f;
        v *= (1.0f - s);
        if (WRITE_SPK) spk[idx + (size_t)t * stride] = __float2bfloat16(s);
        cnt += s;
    }
    mean_out[idx] = cnt * (1.0f / 128.0f);
}

// 3-way bf16 split: w == hi + mid + lo exactly (8+8+8 mantissa bits)
__global__ void __launch_bounds__(256)
wsplit_kernel(const float* __restrict__ w, __nv_bfloat16* __restrict__ o, int n)
{
    int i = blockIdx.x * blockDim.x + threadIdx.x;
    if (i >= n) return;
    float x = w[i];
    __nv_bfloat16 h = __float2bfloat16(x);
    float r1 = x - __bfloat162float(h);
    __nv_bfloat16 m = __float2bfloat16(r1);
    float r2 = r1 - __bfloat162float(m);
    __nv_bfloat16 l = __float2bfloat16(r2);
    o[i] = h; o[n + i] = m; o[2 * n + i] = l;
}

// ---------------------------------------------------------------------------
extern "C" void kernel_launch(void* const* d_in, const int* in_sizes, int n_in,
                              void* d_out, int out_size)
{
    const float* spikes = (const float*)d_in[0];   // (T, B, NLAB) fp32
    const float* W1     = (const float*)d_in[1];   // (HID, NLAB)
    const float* W2     = (const float*)d_in[2];   // (SEM, HID)
    float* out = (float*)d_out;                    // [mean1 | mean2]

    __nv_bfloat16 *spk1, *ws2;
    float* Ibuf;
    cudaGetSymbolAddress((void**)&spk1, g_spk1);
    cudaGetSymbolAddress((void**)&Ibuf, g_I);
    cudaGetSymbolAddress((void**)&ws2,  g_ws2);

    cudaFuncSetAttribute(gemm3s<1024>, cudaFuncAttributeMaxDynamicSharedMemorySize, SMEM_BYTES);

    // W2 splits (independent; overlaps nothing it shouldn't)
    wsplit_kernel<<<(SEM * HID) / 256, 256>>>(W2, ws2, SEM * HID);

    // layer 1: bit-exact fp32 GEMM (packed f32x2), then LIF -> bf16 spikes
    gemm_f32x2<<<dim3(HID / 128, MROWS / 128), 256>>>(spikes, W1, Ibuf,
                                                      MROWS, HID, NLAB);
    lif_kernel<true><<<(BATCH * HID) / 256, 256>>>(Ibuf, spk1, out);

    // layer 2: HMMA 3-split
    gemm3s<1024><<<dim3(SEM / BN2, MROWS / BM2), 256, SMEM_BYTES>>>(spk1, ws2, Ibuf);
    lif_kernel<false><<<(BATCH * SEM) / 256, 256>>>(Ibuf, nullptr, out + (size_t)BATCH * HID);
}